// round 2
// baseline (speedup 1.0000x reference)
#include <cuda_runtime.h>
#include <math.h>
#include <stdint.h>

// Problem constants
#define BB   4
#define LL   1024
#define DD   1024
#define NH   16
#define HH   64
#define RR   2048
#define LOG2E 1.4426950408889634f

// ---------------------------------------------------------------------------
// Device scratch (no allocations allowed -> __device__ globals)
// ---------------------------------------------------------------------------
__device__ float g_QW[BB * NH * LL * HH];   // qh + r_w_bias, [b][n][l][h]
__device__ float g_QR[BB * NH * LL * HH];   // qh + r_r_bias
__device__ float g_KH[BB * NH * LL * HH];
__device__ float g_VH[BB * NH * LL * HH];
__device__ float g_RP[NH * RR * HH];        // r = pos_enc @ r_kernel, [n][r][h]
__device__ float g_OUT[BB * NH * LL * HH];  // attention output

__device__ __forceinline__ float fexp2(float x) {
    float y;
    asm("ex2.approx.ftz.f32 %0, %1;" : "=f"(y) : "f"(x));
    return y;
}

// ---------------------------------------------------------------------------
// Kernel 1: QKV projection GEMM.  Y(4096 x 1024) = X(4096 x 1024) @ W(1024 x 1024)
// 128x128 block tile, K-tile 8, 256 threads, 8x8 per-thread register tile.
// mode 0: q -> g_QW (+bias0) and g_QR (+bias1);  mode 1: k -> g_KH; mode 2: v -> g_VH
// ---------------------------------------------------------------------------
__global__ __launch_bounds__(256) void proj_kernel(
    const float* __restrict__ A, const float* __restrict__ W,
    const float* __restrict__ bias0, const float* __restrict__ bias1, int mode)
{
    __shared__ float As[8][128];
    __shared__ float Bs[8][128];
    const int tid  = threadIdx.x;
    const int m0   = blockIdx.y * 128;
    const int n0   = blockIdx.x * 128;
    const int arow = tid >> 1, acol = (tid & 1) * 4;
    const int brow = tid >> 5, bcol = (tid & 31) * 4;
    const int ty   = tid >> 4, tx = tid & 15;

    float acc[8][8];
#pragma unroll
    for (int i = 0; i < 8; i++)
#pragma unroll
        for (int j = 0; j < 8; j++) acc[i][j] = 0.f;

    for (int k0 = 0; k0 < DD; k0 += 8) {
        float4 av = *(const float4*)(A + (size_t)(m0 + arow) * DD + k0 + acol);
        float4 bv = *(const float4*)(W + (size_t)(k0 + brow) * (NH * HH) + n0 + bcol);
        __syncthreads();
        As[acol + 0][arow] = av.x; As[acol + 1][arow] = av.y;
        As[acol + 2][arow] = av.z; As[acol + 3][arow] = av.w;
        *(float4*)&Bs[brow][bcol] = bv;
        __syncthreads();
#pragma unroll
        for (int kk = 0; kk < 8; kk++) {
            float a[8], b[8];
            *(float4*)&a[0] = *(float4*)&As[kk][ty * 8];
            *(float4*)&a[4] = *(float4*)&As[kk][ty * 8 + 4];
            *(float4*)&b[0] = *(float4*)&Bs[kk][tx * 8];
            *(float4*)&b[4] = *(float4*)&Bs[kk][tx * 8 + 4];
#pragma unroll
            for (int i = 0; i < 8; i++)
#pragma unroll
                for (int j = 0; j < 8; j++)
                    acc[i][j] = fmaf(a[i], b[j], acc[i][j]);
        }
    }

    const int coln = n0 + tx * 8;         // 8 consecutive cols, same head (h0..h0+7)
    const int hn   = coln >> 6;           // head index
    const int h0   = coln & 63;
#pragma unroll
    for (int i = 0; i < 8; i++) {
        int row = m0 + ty * 8 + i;
        int bidx = row >> 10, l = row & 1023;
        size_t base = ((size_t)(bidx * NH + hn) * LL + l) * HH + h0;
        float o0[8];
#pragma unroll
        for (int j = 0; j < 8; j++) o0[j] = acc[i][j] + bias0[coln + j];
        if (mode == 0) {
            float o1[8];
#pragma unroll
            for (int j = 0; j < 8; j++) o1[j] = acc[i][j] + bias1[coln + j];
            *(float4*)(g_QW + base)     = make_float4(o0[0], o0[1], o0[2], o0[3]);
            *(float4*)(g_QW + base + 4) = make_float4(o0[4], o0[5], o0[6], o0[7]);
            *(float4*)(g_QR + base)     = make_float4(o1[0], o1[1], o1[2], o1[3]);
            *(float4*)(g_QR + base + 4) = make_float4(o1[4], o1[5], o1[6], o1[7]);
        } else if (mode == 1) {
            *(float4*)(g_KH + base)     = make_float4(o0[0], o0[1], o0[2], o0[3]);
            *(float4*)(g_KH + base + 4) = make_float4(o0[4], o0[5], o0[6], o0[7]);
        } else {
            *(float4*)(g_VH + base)     = make_float4(o0[0], o0[1], o0[2], o0[3]);
            *(float4*)(g_VH + base + 4) = make_float4(o0[4], o0[5], o0[6], o0[7]);
        }
    }
}

// ---------------------------------------------------------------------------
// Kernel 2: r projection.  RP[n, r, h] = pos_enc(R x D) @ r_kernel[n](D x H)
// 64x64 tile, K-tile 16, 256 threads, 4x4 per thread.  grid = (R/64, NH)
// ---------------------------------------------------------------------------
__global__ __launch_bounds__(256) void rp_kernel(
    const float* __restrict__ A, const float* __restrict__ RK)
{
    __shared__ float As[16][64];
    __shared__ float Bs[16][64];
    const int tid = threadIdx.x;
    const int r0  = blockIdx.x * 64;
    const int n   = blockIdx.y;
    const float* Bm = RK + (size_t)n * DD * HH;
    const int arow = tid >> 2,  acol = (tid & 3) * 4;
    const int brow = tid >> 4,  bcol = (tid & 15) * 4;
    const int ty   = tid >> 4,  tx   = tid & 15;

    float acc[4][4];
#pragma unroll
    for (int i = 0; i < 4; i++)
#pragma unroll
        for (int j = 0; j < 4; j++) acc[i][j] = 0.f;

    for (int k0 = 0; k0 < DD; k0 += 16) {
        float4 av = *(const float4*)(A + (size_t)(r0 + arow) * DD + k0 + acol);
        float4 bv = *(const float4*)(Bm + (size_t)(k0 + brow) * HH + bcol);
        __syncthreads();
        As[acol + 0][arow] = av.x; As[acol + 1][arow] = av.y;
        As[acol + 2][arow] = av.z; As[acol + 3][arow] = av.w;
        *(float4*)&Bs[brow][bcol] = bv;
        __syncthreads();
#pragma unroll
        for (int kk = 0; kk < 16; kk++) {
            float a[4], b[4];
            *(float4*)a = *(float4*)&As[kk][ty * 4];
            *(float4*)b = *(float4*)&Bs[kk][tx * 4];
#pragma unroll
            for (int i = 0; i < 4; i++)
#pragma unroll
                for (int j = 0; j < 4; j++)
                    acc[i][j] = fmaf(a[i], b[j], acc[i][j]);
        }
    }
#pragma unroll
    for (int i = 0; i < 4; i++) {
        size_t base = ((size_t)n * RR + r0 + ty * 4 + i) * HH + tx * 4;
        *(float4*)(g_RP + base) = make_float4(acc[i][0], acc[i][1], acc[i][2], acc[i][3]);
    }
}

// ---------------------------------------------------------------------------
// Kernel 3: fused flash attention with relative-position band gather.
// Grid: (L/64 query tiles, B*N).  256 threads, 64x64 score tile, 4x4/thread.
// Relative shift identity: pos_shifted[l,m] = qr_l . r[L + m - l]
// ---------------------------------------------------------------------------
#define ATTN_SMEM_FLOATS (4096*4 + 8192*2 + 4096 + 64)

__global__ __launch_bounds__(256) void attn_kernel(const int* __restrict__ pad)
{
    extern __shared__ float sm[];
    float* qw_s  = sm;                 // [h][i]  64x64
    float* qr_s  = qw_s  + 4096;       // [h][i]
    float* k_s   = qr_s  + 4096;       // [h][j]
    float* v_s   = k_s   + 4096;       // [j][h]
    float* r_s   = v_s   + 4096;       // [h][c]  64x128
    float* pos_s = r_s   + 8192;       // [i][c]  64x128
    float* p_s   = pos_s + 8192;       // [j][i]  64x64
    float* pen_s = p_s   + 4096;       // [64]

    const int tid = threadIdx.x;
    const int ty  = tid >> 4, tx = tid & 15;
    const int bn  = blockIdx.y;            // b*NH + n
    const int b   = bn >> 4;
    const int n   = bn & 15;
    const int l0  = blockIdx.x * 64;

    // Load Q tiles (transposed to [h][i])
#pragma unroll
    for (int rep = 0; rep < 4; rep++) {
        int idx = tid + rep * 256;
        int i = idx >> 4, hq = (idx & 15) * 4;
        size_t gi = ((size_t)bn * LL + l0 + i) * HH + hq;
        float4 a = *(const float4*)(g_QW + gi);
        qw_s[(hq + 0) * 64 + i] = a.x; qw_s[(hq + 1) * 64 + i] = a.y;
        qw_s[(hq + 2) * 64 + i] = a.z; qw_s[(hq + 3) * 64 + i] = a.w;
        float4 c = *(const float4*)(g_QR + gi);
        qr_s[(hq + 0) * 64 + i] = c.x; qr_s[(hq + 1) * 64 + i] = c.y;
        qr_s[(hq + 2) * 64 + i] = c.z; qr_s[(hq + 3) * 64 + i] = c.w;
    }

    float oacc[4][4];
#pragma unroll
    for (int i = 0; i < 4; i++)
#pragma unroll
        for (int j = 0; j < 4; j++) oacc[i][j] = 0.f;
    float mrow[4] = {-INFINITY, -INFINITY, -INFINITY, -INFINITY};
    float lrow[4] = {0.f, 0.f, 0.f, 0.f};

    for (int kt = 0; kt < LL / 64; kt++) {
        const int m0   = kt * 64;
        const int rel0 = LL + m0 - l0 - 63;

        __syncthreads();   // previous iteration done reading smem
        // K (transposed to [h][j]) and V (direct [j][h])
#pragma unroll
        for (int rep = 0; rep < 4; rep++) {
            int idx = tid + rep * 256;
            int j = idx >> 4, hq = (idx & 15) * 4;
            size_t gi = ((size_t)bn * LL + m0 + j) * HH + hq;
            float4 kv = *(const float4*)(g_KH + gi);
            k_s[(hq + 0) * 64 + j] = kv.x; k_s[(hq + 1) * 64 + j] = kv.y;
            k_s[(hq + 2) * 64 + j] = kv.z; k_s[(hq + 3) * 64 + j] = kv.w;
            float4 vv = *(const float4*)(g_VH + gi);
            *(float4*)&v_s[j * 64 + hq] = vv;
        }
        // r band (transposed to [h][c]), c in [0,128)
#pragma unroll
        for (int rep = 0; rep < 8; rep++) {
            int idx = tid + rep * 256;
            int c = idx >> 4, hq = (idx & 15) * 4;
            int rel = rel0 + c;
            rel = rel < 0 ? 0 : (rel > RR - 1 ? RR - 1 : rel);
            float4 rv = *(const float4*)(g_RP + ((size_t)n * RR + rel) * HH + hq);
            r_s[(hq + 0) * 128 + c] = rv.x; r_s[(hq + 1) * 128 + c] = rv.y;
            r_s[(hq + 2) * 128 + c] = rv.z; r_s[(hq + 3) * 128 + c] = rv.w;
        }
        // padding arrives as 32-bit (int32 or float32 0/1) -> nonzero bits = padded
        if (tid < 64) pen_s[tid] = (pad[b * LL + m0 + tid] != 0) ? -1.0e6f : 0.0f;
        __syncthreads();

        // Phase A: S_qk = QW . K^T
        float sacc[4][4];
#pragma unroll
        for (int i = 0; i < 4; i++)
#pragma unroll
            for (int j = 0; j < 4; j++) sacc[i][j] = 0.f;
#pragma unroll 8
        for (int h = 0; h < 64; h++) {
            float a[4], bv[4];
            *(float4*)a  = *(float4*)&qw_s[h * 64 + ty * 4];
            *(float4*)bv = *(float4*)&k_s[h * 64 + tx * 4];
#pragma unroll
            for (int i = 0; i < 4; i++)
#pragma unroll
                for (int j = 0; j < 4; j++)
                    sacc[i][j] = fmaf(a[i], bv[j], sacc[i][j]);
        }

        // Phase B: band GEMM  P[i][c] = QR . R^T  (c covers 128-wide band)
        {
            float pacc[4][8];
#pragma unroll
            for (int i = 0; i < 4; i++)
#pragma unroll
                for (int u = 0; u < 8; u++) pacc[i][u] = 0.f;
#pragma unroll 8
            for (int h = 0; h < 64; h++) {
                float a[4], c[8];
                *(float4*)a     = *(float4*)&qr_s[h * 64 + ty * 4];
                *(float4*)&c[0] = *(float4*)&r_s[h * 128 + tx * 8];
                *(float4*)&c[4] = *(float4*)&r_s[h * 128 + tx * 8 + 4];
#pragma unroll
                for (int i = 0; i < 4; i++)
#pragma unroll
                    for (int u = 0; u < 8; u++)
                        pacc[i][u] = fmaf(a[i], c[u], pacc[i][u]);
            }
#pragma unroll
            for (int i = 0; i < 4; i++) {
                *(float4*)&pos_s[(ty * 4 + i) * 128 + tx * 8] =
                    make_float4(pacc[i][0], pacc[i][1], pacc[i][2], pacc[i][3]);
                *(float4*)&pos_s[(ty * 4 + i) * 128 + tx * 8 + 4] =
                    make_float4(pacc[i][4], pacc[i][5], pacc[i][6], pacc[i][7]);
            }
        }
        __syncthreads();

        // Combine, mask, online softmax (base 2: identical math to exp-softmax)
        float t[4][4];
#pragma unroll
        for (int ii = 0; ii < 4; ii++) {
            int i = ty * 4 + ii;
#pragma unroll
            for (int jj = 0; jj < 4; jj++) {
                int j = tx * 4 + jj;
                int c = j - i + 63;
                float s = (sacc[ii][jj] + pos_s[i * 128 + c]) * 0.125f + pen_s[j];
                t[ii][jj] = s * LOG2E;
            }
        }
        float alpha[4];
#pragma unroll
        for (int ii = 0; ii < 4; ii++) {
            float mx = fmaxf(fmaxf(t[ii][0], t[ii][1]), fmaxf(t[ii][2], t[ii][3]));
#pragma unroll
            for (int d = 1; d < 16; d <<= 1)
                mx = fmaxf(mx, __shfl_xor_sync(0xffffffffu, mx, d));
            float mnew = fmaxf(mrow[ii], mx);
            alpha[ii]  = fexp2(mrow[ii] - mnew);
            mrow[ii]   = mnew;
            float ssum = 0.f;
#pragma unroll
            for (int jj = 0; jj < 4; jj++) {
                float p = fexp2(t[ii][jj] - mnew);
                t[ii][jj] = p;
                ssum += p;
            }
#pragma unroll
            for (int d = 1; d < 16; d <<= 1)
                ssum += __shfl_xor_sync(0xffffffffu, ssum, d);
            lrow[ii] = lrow[ii] * alpha[ii] + ssum;
        }
        // store P transposed [j][i], rescale O
#pragma unroll
        for (int ii = 0; ii < 4; ii++)
#pragma unroll
            for (int jj = 0; jj < 4; jj++)
                p_s[(tx * 4 + jj) * 64 + (ty * 4 + ii)] = t[ii][jj];
#pragma unroll
        for (int ii = 0; ii < 4; ii++)
#pragma unroll
            for (int hh = 0; hh < 4; hh++)
                oacc[ii][hh] *= alpha[ii];
        __syncthreads();

        // PV accumulate
#pragma unroll 8
        for (int j = 0; j < 64; j++) {
            float p[4], vv[4];
            *(float4*)p  = *(float4*)&p_s[j * 64 + ty * 4];
            *(float4*)vv = *(float4*)&v_s[j * 64 + tx * 4];
#pragma unroll
            for (int ii = 0; ii < 4; ii++)
#pragma unroll
                for (int hh = 0; hh < 4; hh++)
                    oacc[ii][hh] = fmaf(p[ii], vv[hh], oacc[ii][hh]);
        }
    }

#pragma unroll
    for (int ii = 0; ii < 4; ii++) {
        float inv = 1.0f / lrow[ii];
        size_t base = ((size_t)bn * LL + l0 + ty * 4 + ii) * HH + tx * 4;
        *(float4*)(g_OUT + base) = make_float4(oacc[ii][0] * inv, oacc[ii][1] * inv,
                                               oacc[ii][2] * inv, oacc[ii][3] * inv);
    }
}

// ---------------------------------------------------------------------------
// Kernel 4: post projection + residual.  X = OUT(bnlh) @ post_w + q + post_b
// Same 128x128x8 structure as proj_kernel, A gathered from [b][n][l][h].
// ---------------------------------------------------------------------------
__global__ __launch_bounds__(256) void post_kernel(
    const float* __restrict__ resid, const float* __restrict__ W,
    const float* __restrict__ bias, float* __restrict__ Y)
{
    __shared__ float As[8][128];
    __shared__ float Bs[8][128];
    const int tid  = threadIdx.x;
    const int m0   = blockIdx.y * 128;
    const int n0   = blockIdx.x * 128;
    const int arow = tid >> 1, acol = (tid & 1) * 4;
    const int brow = tid >> 5, bcol = (tid & 31) * 4;
    const int ty   = tid >> 4, tx = tid & 15;

    const int row  = m0 + arow;
    const int bidx = row >> 10, l = row & 1023;

    float acc[8][8];
#pragma unroll
    for (int i = 0; i < 8; i++)
#pragma unroll
        for (int j = 0; j < 8; j++) acc[i][j] = 0.f;

    for (int k0 = 0; k0 < NH * HH; k0 += 8) {
        int kk0 = k0 + acol;
        int hn = kk0 >> 6, h = kk0 & 63;
        float4 av = *(const float4*)(g_OUT + ((size_t)(bidx * NH + hn) * LL + l) * HH + h);
        float4 bv = *(const float4*)(W + (size_t)(k0 + brow) * DD + n0 + bcol);
        __syncthreads();
        As[acol + 0][arow] = av.x; As[acol + 1][arow] = av.y;
        As[acol + 2][arow] = av.z; As[acol + 3][arow] = av.w;
        *(float4*)&Bs[brow][bcol] = bv;
        __syncthreads();
#pragma unroll
        for (int kk = 0; kk < 8; kk++) {
            float a[8], b[8];
            *(float4*)&a[0] = *(float4*)&As[kk][ty * 8];
            *(float4*)&a[4] = *(float4*)&As[kk][ty * 8 + 4];
            *(float4*)&b[0] = *(float4*)&Bs[kk][tx * 8];
            *(float4*)&b[4] = *(float4*)&Bs[kk][tx * 8 + 4];
#pragma unroll
            for (int i = 0; i < 8; i++)
#pragma unroll
                for (int j = 0; j < 8; j++)
                    acc[i][j] = fmaf(a[i], b[j], acc[i][j]);
        }
    }

    const int coln = n0 + tx * 8;
#pragma unroll
    for (int i = 0; i < 8; i++) {
        int orow = m0 + ty * 8 + i;
        size_t base = (size_t)orow * DD + coln;
        float o[8];
#pragma unroll
        for (int j = 0; j < 8; j++)
            o[j] = acc[i][j] + resid[base + j] + bias[coln + j];
        *(float4*)(Y + base)     = make_float4(o[0], o[1], o[2], o[3]);
        *(float4*)(Y + base + 4) = make_float4(o[4], o[5], o[6], o[7]);
    }
}

// ---------------------------------------------------------------------------
// Kernel 5: LayerNorm over D=1024, one block per row, in-place on d_out.
// ---------------------------------------------------------------------------
__global__ __launch_bounds__(256) void ln_kernel(
    float* __restrict__ X, const float* __restrict__ g, const float* __restrict__ bta)
{
    __shared__ float red[8];
    const int row = blockIdx.x;
    const int t   = threadIdx.x;
    float4 x = *(float4*)(X + (size_t)row * DD + t * 4);

    float s = x.x + x.y + x.z + x.w;
#pragma unroll
    for (int d = 16; d; d >>= 1) s += __shfl_xor_sync(0xffffffffu, s, d);
    if ((t & 31) == 0) red[t >> 5] = s;
    __syncthreads();
    float tot = red[0] + red[1] + red[2] + red[3] + red[4] + red[5] + red[6] + red[7];
    float mu = tot * (1.0f / DD);
    __syncthreads();

    float dx0 = x.x - mu, dx1 = x.y - mu, dx2 = x.z - mu, dx3 = x.w - mu;
    float sq = dx0 * dx0 + dx1 * dx1 + dx2 * dx2 + dx3 * dx3;
#pragma unroll
    for (int d = 16; d; d >>= 1) sq += __shfl_xor_sync(0xffffffffu, sq, d);
    if ((t & 31) == 0) red[t >> 5] = sq;
    __syncthreads();
    float var = (red[0] + red[1] + red[2] + red[3] + red[4] + red[5] + red[6] + red[7]) * (1.0f / DD);
    float rs = rsqrtf(var + 1e-5f);

    float4 gg = *(const float4*)(g + t * 4);
    float4 bb = *(const float4*)(bta + t * 4);
    float4 y = make_float4(dx0 * rs * gg.x + bb.x, dx1 * rs * gg.y + bb.y,
                           dx2 * rs * gg.z + bb.z, dx3 * rs * gg.w + bb.w);
    *(float4*)(X + (size_t)row * DD + t * 4) = y;
}

// ---------------------------------------------------------------------------
// Launch
// ---------------------------------------------------------------------------
extern "C" void kernel_launch(void* const* d_in, const int* in_sizes, int n_in,
                              void* d_out, int out_size)
{
    const float* q   = (const float*)d_in[0];
    const float* k   = (const float*)d_in[1];
    const float* v   = (const float*)d_in[2];
    const float* pe  = (const float*)d_in[3];
    const int*   pad = (const int*)d_in[4];
    const float* q_w = (const float*)d_in[5];
    const float* k_w = (const float*)d_in[6];
    const float* k_b = (const float*)d_in[7];
    const float* v_w = (const float*)d_in[8];
    const float* v_b = (const float*)d_in[9];
    const float* rwb = (const float*)d_in[10];
    const float* rrb = (const float*)d_in[11];
    const float* r_k = (const float*)d_in[12];
    const float* pw  = (const float*)d_in[13];
    const float* pb  = (const float*)d_in[14];
    const float* lg  = (const float*)d_in[15];
    const float* lb  = (const float*)d_in[16];
    float* out = (float*)d_out;

    const int attn_smem = ATTN_SMEM_FLOATS * (int)sizeof(float);
    cudaFuncSetAttribute(attn_kernel, cudaFuncAttributeMaxDynamicSharedMemorySize, attn_smem);

    dim3 g1(8, 32);   // 1024-col x 4096-row in 128x128 tiles
    proj_kernel<<<g1, 256>>>(q, q_w, rwb, rrb, 0);
    proj_kernel<<<g1, 256>>>(k, k_w, k_b, k_b, 1);
    proj_kernel<<<g1, 256>>>(v, v_w, v_b, v_b, 2);
    rp_kernel<<<dim3(RR / 64, NH), 256>>>(pe, r_k);
    attn_kernel<<<dim3(LL / 64, BB * NH), 256, attn_smem>>>(pad);
    post_kernel<<<g1, 256>>>(q, pw, pb, out);
    ln_kernel<<<BB * LL, 256>>>(out, lg, lb);
}

// round 4
// speedup vs baseline: 1.2836x; 1.2836x over previous
#include <cuda_runtime.h>
#include <cuda_bf16.h>
#include <math.h>
#include <stdint.h>

// Problem constants
#define BB   4
#define LL   1024
#define DD   1024
#define NH   16
#define HH   64
#define RR   2048
#define LOG2E 1.4426950408889634f
#define KBYTES 2048        // K=1024 bf16 row stride in bytes

// ---------------------------------------------------------------------------
// Device scratch
// ---------------------------------------------------------------------------
__device__ float g_QW[BB * NH * LL * HH];   // qh + r_w_bias, [b][n][l][h]
__device__ float g_QR[BB * NH * LL * HH];   // qh + r_r_bias
__device__ float g_KH[BB * NH * LL * HH];
__device__ float g_VH[BB * NH * LL * HH];
__device__ float g_RP[NH * RR * HH];        // r = pos_enc @ r_kernel, [n][r][h]
__device__ float g_OUT[BB * NH * LL * HH];  // attention output

// bf16 hi/lo staging (uint4 for 16B alignment). Reused sequentially.
__device__ uint4 g_INhi4[BB * LL * DD / 8];   // 8 MB
__device__ uint4 g_INlo4[BB * LL * DD / 8];
__device__ uint4 g_WThi4[DD * DD / 8];        // 2 MB, [n][k] (K-major, rows = out col)
__device__ uint4 g_WTlo4[DD * DD / 8];

__device__ __forceinline__ float fexp2(float x) {
    float y;
    asm("ex2.approx.ftz.f32 %0, %1;" : "=f"(y) : "f"(x));
    return y;
}
__device__ __forceinline__ uint32_t smem_u32(const void* p) {
    uint32_t a;
    asm("{ .reg .u64 t; cvta.to.shared.u64 t, %1; cvt.u32.u64 %0, t; }" : "=r"(a) : "l"(p));
    return a;
}
__device__ __forceinline__ void ldmx4(uint32_t* r, uint32_t addr) {
    asm volatile("ldmatrix.sync.aligned.m8n8.x4.shared.b16 {%0,%1,%2,%3}, [%4];"
        : "=r"(r[0]), "=r"(r[1]), "=r"(r[2]), "=r"(r[3]) : "r"(addr));
}
__device__ __forceinline__ void mma16816(float* c, const uint32_t* a, const uint32_t* b) {
    asm volatile("mma.sync.aligned.m16n8k16.row.col.f32.bf16.bf16.f32 "
        "{%0,%1,%2,%3}, {%4,%5,%6,%7}, {%8,%9}, {%0,%1,%2,%3};"
        : "+f"(c[0]), "+f"(c[1]), "+f"(c[2]), "+f"(c[3])
        : "r"(a[0]), "r"(a[1]), "r"(a[2]), "r"(a[3]), "r"(b[0]), "r"(b[1]));
}

// ---------------------------------------------------------------------------
// Prepass A: fp32 -> bf16 hi/lo (row-major preserved)
// ---------------------------------------------------------------------------
__global__ __launch_bounds__(256) void cvt_kernel(const float4* __restrict__ src,
                                                  uint32_t* __restrict__ hi,
                                                  uint32_t* __restrict__ lo, int n4)
{
    int i = blockIdx.x * 256 + threadIdx.x;
    if (i >= n4) return;
    float4 x = src[i];
    __nv_bfloat162 h01, h23, l01, l23;
    h01.x = __float2bfloat16_rn(x.x); h01.y = __float2bfloat16_rn(x.y);
    h23.x = __float2bfloat16_rn(x.z); h23.y = __float2bfloat16_rn(x.w);
    l01.x = __float2bfloat16_rn(x.x - __bfloat162float(h01.x));
    l01.y = __float2bfloat16_rn(x.y - __bfloat162float(h01.y));
    l23.x = __float2bfloat16_rn(x.z - __bfloat162float(h23.x));
    l23.y = __float2bfloat16_rn(x.w - __bfloat162float(h23.y));
    hi[i * 2 + 0] = *(uint32_t*)&h01; hi[i * 2 + 1] = *(uint32_t*)&h23;
    lo[i * 2 + 0] = *(uint32_t*)&l01; lo[i * 2 + 1] = *(uint32_t*)&l23;
}

// Prepass B: transpose + convert weights.  src [batch][R][C] fp32 -> dst [batch][C][R] bf16 hi/lo
__global__ void trcvt_kernel(const float* __restrict__ src,
                             __nv_bfloat16* __restrict__ dhi, __nv_bfloat16* __restrict__ dlo,
                             int R, int C)
{
    __shared__ float t[32][33];
    const int bz = blockIdx.z;
    const int c0 = blockIdx.x * 32, r0 = blockIdx.y * 32;
    const int tx = threadIdx.x, ty = threadIdx.y;   // 32 x 8
    const float* s = src + (size_t)bz * R * C;
#pragma unroll
    for (int i = 0; i < 4; i++)
        t[ty + 8 * i][tx] = s[(size_t)(r0 + ty + 8 * i) * C + c0 + tx];
    __syncthreads();
#pragma unroll
    for (int i = 0; i < 4; i++) {
        float v = t[tx][ty + 8 * i];
        __nv_bfloat16 h = __float2bfloat16_rn(v);
        __nv_bfloat16 l = __float2bfloat16_rn(v - __bfloat162float(h));
        size_t o = (size_t)bz * C * R + (size_t)(c0 + ty + 8 * i) * R + r0 + tx;
        dhi[o] = h; dlo[o] = l;
    }
}

// Prepass C: gather g_OUT [b][n][l][h] -> row-major [(b,l)][(n,h)] bf16 hi/lo
__global__ __launch_bounds__(256) void outcvt_kernel(uint32_t* __restrict__ hi,
                                                     uint32_t* __restrict__ lo)
{
    int p = blockIdx.x * 256 + threadIdx.x;
    if (p >= BB * LL * DD / 2) return;
    int row = p >> 9;
    int col = (p & 511) * 2;
    int b = row >> 10, l = row & 1023;
    int n = col >> 6, h = col & 63;
    size_t si = ((size_t)(b * NH + n) * LL + l) * HH + h;
    float v0 = g_OUT[si], v1 = g_OUT[si + 1];
    __nv_bfloat162 hp, lp;
    hp.x = __float2bfloat16_rn(v0); hp.y = __float2bfloat16_rn(v1);
    lp.x = __float2bfloat16_rn(v0 - __bfloat162float(hp.x));
    lp.y = __float2bfloat16_rn(v1 - __bfloat162float(hp.y));
    hi[p] = *(uint32_t*)&hp;
    lo[p] = *(uint32_t*)&lp;
}

// ---------------------------------------------------------------------------
// HMMA GEMM: C[128x128] = A[M x 1024] @ B^T (B stored [n][k]), bf16 hi/lo split.
// 3-term: hi*hi + hi*lo + lo*hi, fp32 accumulate.  256 threads, warp tile 32x64.
// mode 0: g_QW(+aux0) & g_QR(+aux1), bnlh;  1/2: out0(+aux0), bnlh;
// mode 3: out0 = D + aux0[col] + aux2[m*D+col] row-major;  4: rp layout.
// ---------------------------------------------------------------------------
#define STRIDE 80   // smem row stride bytes (64B data + 16B skew): conflict-free ldmatrix

__global__ __launch_bounds__(256) void hgemm(
    const char* __restrict__ Ahi, const char* __restrict__ Alo,
    const char* __restrict__ Bhi, const char* __restrict__ Blo,
    const float* __restrict__ aux0, const float* __restrict__ aux1,
    const float* __restrict__ aux2,
    float* __restrict__ out0, float* __restrict__ out1, int mode)
{
    __shared__ char sA[2][128 * STRIDE];
    __shared__ char sB[2][128 * STRIDE];

    const int tid = threadIdx.x, lane = tid & 31, wid = tid >> 5;
    const int wm = wid >> 1, wn = wid & 1;          // 4 x 2 warp grid
    const int m0 = blockIdx.y * 128, n0 = blockIdx.x * 128;

    float c[2][8][4] = {};

    // gmem<->smem copy coords: 2 threads per 64B row
    const int lrow = tid >> 1;
    const int lseg = (tid & 1) * 32;                // byte offset within row
    const size_t gA = (size_t)(m0 + lrow) * KBYTES + lseg;
    const size_t gB = (size_t)(n0 + lrow) * KBYTES + lseg;
    const int srow = lrow * STRIDE + lseg;
    const char* gp0 = Ahi + gA; const char* gp1 = Alo + gA;
    const char* gp2 = Bhi + gB; const char* gp3 = Blo + gB;
    char* sp0 = sA[0] + srow;  char* sp1 = sA[1] + srow;
    char* sp2 = sB[0] + srow;  char* sp3 = sB[1] + srow;

    // ldmatrix base addresses
    const uint32_t aBaseHi = smem_u32(sA[0]), aBaseLo = smem_u32(sA[1]);
    const uint32_t bBaseHi = smem_u32(sB[0]), bBaseLo = smem_u32(sB[1]);
    const int arow_in = (lane & 7) + ((lane >> 3) & 1) * 8;
    const int ak16    = (lane >> 4) * 16;
    const int brow_in = (lane & 7) + (lane >> 4) * 8;
    const int bk16    = ((lane >> 3) & 1) * 16;
    const uint32_t aOffHi = aBaseHi + (wm * 32 + arow_in) * STRIDE + ak16;
    const uint32_t aOffLo = aBaseLo + (wm * 32 + arow_in) * STRIDE + ak16;
    const uint32_t bOffHi = bBaseHi + (wn * 64 + brow_in) * STRIDE + bk16;
    const uint32_t bOffLo = bBaseLo + (wn * 64 + brow_in) * STRIDE + bk16;

    uint4 pf0a, pf0b, pf1a, pf1b, pf2a, pf2b, pf3a, pf3b;
    pf0a = *(const uint4*)(gp0);      pf0b = *(const uint4*)(gp0 + 16);
    pf1a = *(const uint4*)(gp1);      pf1b = *(const uint4*)(gp1 + 16);
    pf2a = *(const uint4*)(gp2);      pf2b = *(const uint4*)(gp2 + 16);
    pf3a = *(const uint4*)(gp3);      pf3b = *(const uint4*)(gp3 + 16);

    for (int ck = 0; ck < 32; ck++) {
        *(uint4*)(sp0) = pf0a; *(uint4*)(sp0 + 16) = pf0b;
        *(uint4*)(sp1) = pf1a; *(uint4*)(sp1 + 16) = pf1b;
        *(uint4*)(sp2) = pf2a; *(uint4*)(sp2 + 16) = pf2b;
        *(uint4*)(sp3) = pf3a; *(uint4*)(sp3 + 16) = pf3b;
        __syncthreads();
        if (ck < 31) {
            int off = (ck + 1) * 64;
            pf0a = *(const uint4*)(gp0 + off); pf0b = *(const uint4*)(gp0 + off + 16);
            pf1a = *(const uint4*)(gp1 + off); pf1b = *(const uint4*)(gp1 + off + 16);
            pf2a = *(const uint4*)(gp2 + off); pf2b = *(const uint4*)(gp2 + off + 16);
            pf3a = *(const uint4*)(gp3 + off); pf3b = *(const uint4*)(gp3 + off + 16);
        }
#pragma unroll
        for (int ks = 0; ks < 2; ks++) {
            const int kb = ks * 32;
            uint32_t ah[2][4], al[2][4];
#pragma unroll
            for (int mt = 0; mt < 2; mt++) {
                ldmx4(ah[mt], aOffHi + mt * (16 * STRIDE) + kb);
                ldmx4(al[mt], aOffLo + mt * (16 * STRIDE) + kb);
            }
#pragma unroll
            for (int ntp = 0; ntp < 4; ntp++) {
                uint32_t bh[4], bl[4];
                ldmx4(bh, bOffHi + ntp * (16 * STRIDE) + kb);
                ldmx4(bl, bOffLo + ntp * (16 * STRIDE) + kb);
#pragma unroll
                for (int mt = 0; mt < 2; mt++) {
                    mma16816(c[mt][ntp * 2 + 0], ah[mt], bh + 0);
                    mma16816(c[mt][ntp * 2 + 1], ah[mt], bh + 2);
                    mma16816(c[mt][ntp * 2 + 0], ah[mt], bl + 0);
                    mma16816(c[mt][ntp * 2 + 1], ah[mt], bl + 2);
                    mma16816(c[mt][ntp * 2 + 0], al[mt], bh + 0);
                    mma16816(c[mt][ntp * 2 + 1], al[mt], bh + 2);
                }
            }
        }
        __syncthreads();
    }

    // Epilogue: fragment layout row = +g (+8), cols tg*2, tg*2+1
    const int g = lane >> 2, tg = lane & 3;
#pragma unroll
    for (int mt = 0; mt < 2; mt++) {
#pragma unroll
        for (int half = 0; half < 2; half++) {
            const int m = m0 + wm * 32 + mt * 16 + g + half * 8;
#pragma unroll
            for (int nt = 0; nt < 8; nt++) {
                float v0 = c[mt][nt][half * 2 + 0];
                float v1 = c[mt][nt][half * 2 + 1];
                const int coln = n0 + wn * 64 + nt * 8 + tg * 2;
                if (mode <= 2) {
                    int hd = coln >> 6, h = coln & 63;
                    int b = m >> 10, l = m & 1023;
                    size_t o = ((size_t)(b * NH + hd) * LL + l) * HH + h;
                    float2 w0 = make_float2(v0 + aux0[coln], v1 + aux0[coln + 1]);
                    *(float2*)(out0 + o) = w0;
                    if (mode == 0) {
                        float2 w1 = make_float2(v0 + aux1[coln], v1 + aux1[coln + 1]);
                        *(float2*)(out1 + o) = w1;
                    }
                } else if (mode == 3) {
                    size_t o = (size_t)m * DD + coln;
                    float2 res = *(const float2*)(aux2 + o);
                    *(float2*)(out0 + o) =
                        make_float2(v0 + aux0[coln] + res.x, v1 + aux0[coln + 1] + res.y);
                } else {
                    int hd = coln >> 6, h = coln & 63;
                    size_t o = ((size_t)hd * RR + m) * HH + h;
                    *(float2*)(out0 + o) = make_float2(v0, v1);
                }
            }
        }
    }
}

// ---------------------------------------------------------------------------
// Fused flash attention (fp32) — unchanged
// ---------------------------------------------------------------------------
#define ATTN_SMEM_FLOATS (4096*4 + 8192*2 + 4096 + 64)

__global__ __launch_bounds__(256) void attn_kernel(const int* __restrict__ pad)
{
    extern __shared__ float sm[];
    float* qw_s  = sm;
    float* qr_s  = qw_s  + 4096;
    float* k_s   = qr_s  + 4096;
    float* v_s   = k_s   + 4096;
    float* r_s   = v_s   + 4096;
    float* pos_s = r_s   + 8192;
    float* p_s   = pos_s + 8192;
    float* pen_s = p_s   + 4096;

    const int tid = threadIdx.x;
    const int ty  = tid >> 4, tx = tid & 15;
    const int bn  = blockIdx.y;
    const int b   = bn >> 4;
    const int n   = bn & 15;
    const int l0  = blockIdx.x * 64;

#pragma unroll
    for (int rep = 0; rep < 4; rep++) {
        int idx = tid + rep * 256;
        int i = idx >> 4, hq = (idx & 15) * 4;
        size_t gi = ((size_t)bn * LL + l0 + i) * HH + hq;
        float4 a = *(const float4*)(g_QW + gi);
        qw_s[(hq + 0) * 64 + i] = a.x; qw_s[(hq + 1) * 64 + i] = a.y;
        qw_s[(hq + 2) * 64 + i] = a.z; qw_s[(hq + 3) * 64 + i] = a.w;
        float4 c = *(const float4*)(g_QR + gi);
        qr_s[(hq + 0) * 64 + i] = c.x; qr_s[(hq + 1) * 64 + i] = c.y;
        qr_s[(hq + 2) * 64 + i] = c.z; qr_s[(hq + 3) * 64 + i] = c.w;
    }

    float oacc[4][4];
#pragma unroll
    for (int i = 0; i < 4; i++)
#pragma unroll
        for (int j = 0; j < 4; j++) oacc[i][j] = 0.f;
    float mrow[4] = {-INFINITY, -INFINITY, -INFINITY, -INFINITY};
    float lrow[4] = {0.f, 0.f, 0.f, 0.f};

    for (int kt = 0; kt < LL / 64; kt++) {
        const int m0   = kt * 64;
        const int rel0 = LL + m0 - l0 - 63;

        __syncthreads();
#pragma unroll
        for (int rep = 0; rep < 4; rep++) {
            int idx = tid + rep * 256;
            int j = idx >> 4, hq = (idx & 15) * 4;
            size_t gi = ((size_t)bn * LL + m0 + j) * HH + hq;
            float4 kv = *(const float4*)(g_KH + gi);
            k_s[(hq + 0) * 64 + j] = kv.x; k_s[(hq + 1) * 64 + j] = kv.y;
            k_s[(hq + 2) * 64 + j] = kv.z; k_s[(hq + 3) * 64 + j] = kv.w;
            float4 vv = *(const float4*)(g_VH + gi);
            *(float4*)&v_s[j * 64 + hq] = vv;
        }
#pragma unroll
        for (int rep = 0; rep < 8; rep++) {
            int idx = tid + rep * 256;
            int c = idx >> 4, hq = (idx & 15) * 4;
            int rel = rel0 + c;
            rel = rel < 0 ? 0 : (rel > RR - 1 ? RR - 1 : rel);
            float4 rv = *(const float4*)(g_RP + ((size_t)n * RR + rel) * HH + hq);
            r_s[(hq + 0) * 128 + c] = rv.x; r_s[(hq + 1) * 128 + c] = rv.y;
            r_s[(hq + 2) * 128 + c] = rv.z; r_s[(hq + 3) * 128 + c] = rv.w;
        }
        if (tid < 64) pen_s[tid] = (pad[b * LL + m0 + tid] != 0) ? -1.0e6f : 0.0f;
        __syncthreads();

        float sacc[4][4];
#pragma unroll
        for (int i = 0; i < 4; i++)
#pragma unroll
            for (int j = 0; j < 4; j++) sacc[i][j] = 0.f;
#pragma unroll 8
        for (int h = 0; h < 64; h++) {
            float a[4], bv[4];
            *(float4*)a  = *(float4*)&qw_s[h * 64 + ty * 4];
            *(float4*)bv = *(float4*)&k_s[h * 64 + tx * 4];
#pragma unroll
            for (int i = 0; i < 4; i++)
#pragma unroll
                for (int j = 0; j < 4; j++)
                    sacc[i][j] = fmaf(a[i], bv[j], sacc[i][j]);
        }

        {
            float pacc[4][8];
#pragma unroll
            for (int i = 0; i < 4; i++)
#pragma unroll
                for (int u = 0; u < 8; u++) pacc[i][u] = 0.f;
#pragma unroll 8
            for (int h = 0; h < 64; h++) {
                float a[4], cc[8];
                *(float4*)a      = *(float4*)&qr_s[h * 64 + ty * 4];
                *(float4*)&cc[0] = *(float4*)&r_s[h * 128 + tx * 8];
                *(float4*)&cc[4] = *(float4*)&r_s[h * 128 + tx * 8 + 4];
#pragma unroll
                for (int i = 0; i < 4; i++)
#pragma unroll
                    for (int u = 0; u < 8; u++)
                        pacc[i][u] = fmaf(a[i], cc[u], pacc[i][u]);
            }
#pragma unroll
            for (int i = 0; i < 4; i++) {
                *(float4*)&pos_s[(ty * 4 + i) * 128 + tx * 8] =
                    make_float4(pacc[i][0], pacc[i][1], pacc[i][2], pacc[i][3]);
                *(float4*)&pos_s[(ty * 4 + i) * 128 + tx * 8 + 4] =
                    make_float4(pacc[i][4], pacc[i][5], pacc[i][6], pacc[i][7]);
            }
        }
        __syncthreads();

        float t[4][4];
#pragma unroll
        for (int ii = 0; ii < 4; ii++) {
            int i = ty * 4 + ii;
#pragma unroll
            for (int jj = 0; jj < 4; jj++) {
                int j = tx * 4 + jj;
                int cc = j - i + 63;
                float s = (sacc[ii][jj] + pos_s[i * 128 + cc]) * 0.125f + pen_s[j];
                t[ii][jj] = s * LOG2E;
            }
        }
        float alpha[4];
#pragma unroll
        for (int ii = 0; ii < 4; ii++) {
            float mx = fmaxf(fmaxf(t[ii][0], t[ii][1]), fmaxf(t[ii][2], t[ii][3]));
#pragma unroll
            for (int d = 1; d < 16; d <<= 1)
                mx = fmaxf(mx, __shfl_xor_sync(0xffffffffu, mx, d));
            float mnew = fmaxf(mrow[ii], mx);
            alpha[ii]  = fexp2(mrow[ii] - mnew);
            mrow[ii]   = mnew;
            float ssum = 0.f;
#pragma unroll
            for (int jj = 0; jj < 4; jj++) {
                float p = fexp2(t[ii][jj] - mnew);
                t[ii][jj] = p;
                ssum += p;
            }
#pragma unroll
            for (int d = 1; d < 16; d <<= 1)
                ssum += __shfl_xor_sync(0xffffffffu, ssum, d);
            lrow[ii] = lrow[ii] * alpha[ii] + ssum;
        }
#pragma unroll
        for (int ii = 0; ii < 4; ii++)
#pragma unroll
            for (int jj = 0; jj < 4; jj++)
                p_s[(tx * 4 + jj) * 64 + (ty * 4 + ii)] = t[ii][jj];
#pragma unroll
        for (int ii = 0; ii < 4; ii++)
#pragma unroll
            for (int hh = 0; hh < 4; hh++)
                oacc[ii][hh] *= alpha[ii];
        __syncthreads();

#pragma unroll 8
        for (int j = 0; j < 64; j++) {
            float p[4], vv[4];
            *(float4*)p  = *(float4*)&p_s[j * 64 + ty * 4];
            *(float4*)vv = *(float4*)&v_s[j * 64 + tx * 4];
#pragma unroll
            for (int ii = 0; ii < 4; ii++)
#pragma unroll
                for (int hh = 0; hh < 4; hh++)
                    oacc[ii][hh] = fmaf(p[ii], vv[hh], oacc[ii][hh]);
        }
    }

#pragma unroll
    for (int ii = 0; ii < 4; ii++) {
        float inv = 1.0f / lrow[ii];
        size_t base = ((size_t)bn * LL + l0 + ty * 4 + ii) * HH + tx * 4;
        *(float4*)(g_OUT + base) = make_float4(oacc[ii][0] * inv, oacc[ii][1] * inv,
                                               oacc[ii][2] * inv, oacc[ii][3] * inv);
    }
}

// ---------------------------------------------------------------------------
// LayerNorm
// ---------------------------------------------------------------------------
__global__ __launch_bounds__(256) void ln_kernel(
    float* __restrict__ X, const float* __restrict__ g, const float* __restrict__ bta)
{
    __shared__ float red[8];
    const int row = blockIdx.x;
    const int t   = threadIdx.x;
    float4 x = *(float4*)(X + (size_t)row * DD + t * 4);

    float s = x.x + x.y + x.z + x.w;
#pragma unroll
    for (int d = 16; d; d >>= 1) s += __shfl_xor_sync(0xffffffffu, s, d);
    if ((t & 31) == 0) red[t >> 5] = s;
    __syncthreads();
    float tot = red[0] + red[1] + red[2] + red[3] + red[4] + red[5] + red[6] + red[7];
    float mu = tot * (1.0f / DD);
    __syncthreads();

    float dx0 = x.x - mu, dx1 = x.y - mu, dx2 = x.z - mu, dx3 = x.w - mu;
    float sq = dx0 * dx0 + dx1 * dx1 + dx2 * dx2 + dx3 * dx3;
#pragma unroll
    for (int d = 16; d; d >>= 1) sq += __shfl_xor_sync(0xffffffffu, sq, d);
    if ((t & 31) == 0) red[t >> 5] = sq;
    __syncthreads();
    float var = (red[0] + red[1] + red[2] + red[3] + red[4] + red[5] + red[6] + red[7]) * (1.0f / DD);
    float rs = rsqrtf(var + 1e-5f);

    float4 gg = *(const float4*)(g + t * 4);
    float4 bb = *(const float4*)(bta + t * 4);
    float4 y = make_float4(dx0 * rs * gg.x + bb.x, dx1 * rs * gg.y + bb.y,
                           dx2 * rs * gg.z + bb.z, dx3 * rs * gg.w + bb.w);
    *(float4*)(X + (size_t)row * DD + t * 4) = y;
}

// ---------------------------------------------------------------------------
// Launch
// ---------------------------------------------------------------------------
extern "C" void kernel_launch(void* const* d_in, const int* in_sizes, int n_in,
                              void* d_out, int out_size)
{
    const float* q   = (const float*)d_in[0];
    const float* k   = (const float*)d_in[1];
    const float* v   = (const float*)d_in[2];
    const float* pe  = (const float*)d_in[3];
    const int*   pad = (const int*)d_in[4];
    const float* q_w = (const float*)d_in[5];
    const float* k_w = (const float*)d_in[6];
    const float* k_b = (const float*)d_in[7];
    const float* v_w = (const float*)d_in[8];
    const float* v_b = (const float*)d_in[9];
    const float* rwb = (const float*)d_in[10];
    const float* rrb = (const float*)d_in[11];
    const float* r_k = (const float*)d_in[12];
    const float* pw  = (const float*)d_in[13];
    const float* pb  = (const float*)d_in[14];
    const float* lg  = (const float*)d_in[15];
    const float* lb  = (const float*)d_in[16];
    float* out = (float*)d_out;

    const int attn_smem = ATTN_SMEM_FLOATS * (int)sizeof(float);
    cudaFuncSetAttribute(attn_kernel, cudaFuncAttributeMaxDynamicSharedMemorySize, attn_smem);

    char *inhi, *inlo, *wthi, *wtlo;
    cudaGetSymbolAddress((void**)&inhi, g_INhi4);
    cudaGetSymbolAddress((void**)&inlo, g_INlo4);
    cudaGetSymbolAddress((void**)&wthi, g_WThi4);
    cudaGetSymbolAddress((void**)&wtlo, g_WTlo4);
    float *qw, *qr, *kh, *vh, *rp;
    cudaGetSymbolAddress((void**)&qw, g_QW);
    cudaGetSymbolAddress((void**)&qr, g_QR);
    cudaGetSymbolAddress((void**)&kh, g_KH);
    cudaGetSymbolAddress((void**)&vh, g_VH);
    cudaGetSymbolAddress((void**)&rp, g_RP);

    dim3 gg(8, 32);            // N=1024/128, M=4096/128
    dim3 tr(32, 8);
    const int n4_in = BB * LL * DD / 4;

    // ---- q projection ----
    cvt_kernel<<<(n4_in + 255) / 256, 256>>>((const float4*)q, (uint32_t*)inhi, (uint32_t*)inlo, n4_in);
    trcvt_kernel<<<dim3(32, 32, 1), tr>>>(q_w, (__nv_bfloat16*)wthi, (__nv_bfloat16*)wtlo, DD, DD);
    hgemm<<<gg, 256>>>(inhi, inlo, wthi, wtlo, rwb, rrb, nullptr, qw, qr, 0);
    // ---- k projection ----
    cvt_kernel<<<(n4_in + 255) / 256, 256>>>((const float4*)k, (uint32_t*)inhi, (uint32_t*)inlo, n4_in);
    trcvt_kernel<<<dim3(32, 32, 1), tr>>>(k_w, (__nv_bfloat16*)wthi, (__nv_bfloat16*)wtlo, DD, DD);
    hgemm<<<gg, 256>>>(inhi, inlo, wthi, wtlo, k_b, nullptr, nullptr, kh, nullptr, 1);
    // ---- v projection ----
    cvt_kernel<<<(n4_in + 255) / 256, 256>>>((const float4*)v, (uint32_t*)inhi, (uint32_t*)inlo, n4_in);
    trcvt_kernel<<<dim3(32, 32, 1), tr>>>(v_w, (__nv_bfloat16*)wthi, (__nv_bfloat16*)wtlo, DD, DD);
    hgemm<<<gg, 256>>>(inhi, inlo, wthi, wtlo, v_b, nullptr, nullptr, vh, nullptr, 2);
    // ---- rp ----
    const int n4_pe = RR * DD / 4;
    cvt_kernel<<<(n4_pe + 255) / 256, 256>>>((const float4*)pe, (uint32_t*)inhi, (uint32_t*)inlo, n4_pe);
    trcvt_kernel<<<dim3(2, 32, 16), tr>>>(r_k, (__nv_bfloat16*)wthi, (__nv_bfloat16*)wtlo, DD, HH);
    hgemm<<<dim3(8, 16), 256>>>(inhi, inlo, wthi, wtlo, nullptr, nullptr, nullptr, rp, nullptr, 4);
    // ---- attention ----
    attn_kernel<<<dim3(LL / 64, BB * NH), 256, attn_smem>>>(pad);
    // ---- post projection + residual ----
    outcvt_kernel<<<(BB * LL * DD / 2 + 255) / 256, 256>>>((uint32_t*)inhi, (uint32_t*)inlo);
    trcvt_kernel<<<dim3(32, 32, 1), tr>>>(pw, (__nv_bfloat16*)wthi, (__nv_bfloat16*)wtlo, DD, DD);
    hgemm<<<gg, 256>>>(inhi, inlo, wthi, wtlo, pb, nullptr, q, out, nullptr, 3);
    // ---- layernorm ----
    ln_kernel<<<BB * LL, 256>>>(out, lg, lb);
}

// round 5
// speedup vs baseline: 2.5325x; 1.9729x over previous
#include <cuda_runtime.h>
#include <cuda_bf16.h>
#include <math.h>
#include <stdint.h>

// Problem constants
#define BB   4
#define LL   1024
#define DD   1024
#define NH   16
#define HH   64
#define RR   2048
#define LOG2E 1.4426950408889634f
#define KBYTES 2048        // K=1024 bf16 row stride in bytes

// ---------------------------------------------------------------------------
// Device scratch
// ---------------------------------------------------------------------------
// bf16 hi/lo staging for GEMM A inputs (q/k/v/pe rows; attention output rows)
__device__ uint4 g_INhi4[BB * LL * DD / 8];   // 8 MB
__device__ uint4 g_INlo4[BB * LL * DD / 8];
__device__ uint4 g_WThi4[DD * DD / 8];        // 2 MB, [n][k]
__device__ uint4 g_WTlo4[DD * DD / 8];

// projection outputs, bf16 hi/lo pairs (uint32 = bf16x2), [b][n][l][h]/2
__device__ uint32_t g_QWh2[BB * NH * LL * HH / 2];
__device__ uint32_t g_QWl2[BB * NH * LL * HH / 2];
__device__ uint32_t g_QRh2[BB * NH * LL * HH / 2];
__device__ uint32_t g_QRl2[BB * NH * LL * HH / 2];
__device__ uint32_t g_KHh2[BB * NH * LL * HH / 2];
__device__ uint32_t g_KHl2[BB * NH * LL * HH / 2];
__device__ uint32_t g_VHh2[BB * NH * LL * HH / 2];
__device__ uint32_t g_VHl2[BB * NH * LL * HH / 2];
__device__ uint32_t g_RPh2[NH * RR * HH / 2];
__device__ uint32_t g_RPl2[NH * RR * HH / 2];

__device__ __forceinline__ uint32_t smem_u32(const void* p) {
    uint32_t a;
    asm("{ .reg .u64 t; cvta.to.shared.u64 t, %1; cvt.u32.u64 %0, t; }" : "=r"(a) : "l"(p));
    return a;
}
__device__ __forceinline__ void ldmx4(uint32_t* r, uint32_t addr) {
    asm volatile("ldmatrix.sync.aligned.m8n8.x4.shared.b16 {%0,%1,%2,%3}, [%4];"
        : "=r"(r[0]), "=r"(r[1]), "=r"(r[2]), "=r"(r[3]) : "r"(addr));
}
__device__ __forceinline__ void ldmx4t(uint32_t* r, uint32_t addr) {
    asm volatile("ldmatrix.sync.aligned.m8n8.x4.trans.shared.b16 {%0,%1,%2,%3}, [%4];"
        : "=r"(r[0]), "=r"(r[1]), "=r"(r[2]), "=r"(r[3]) : "r"(addr));
}
__device__ __forceinline__ void mma16816(float* c, const uint32_t* a, const uint32_t* b) {
    asm volatile("mma.sync.aligned.m16n8k16.row.col.f32.bf16.bf16.f32 "
        "{%0,%1,%2,%3}, {%4,%5,%6,%7}, {%8,%9}, {%0,%1,%2,%3};"
        : "+f"(c[0]), "+f"(c[1]), "+f"(c[2]), "+f"(c[3])
        : "r"(a[0]), "r"(a[1]), "r"(a[2]), "r"(a[3]), "r"(b[0]), "r"(b[1]));
}
__device__ __forceinline__ void pack_hilo(float a, float b, uint32_t& hi, uint32_t& lo) {
    __nv_bfloat16 ha = __float2bfloat16_rn(a), hb = __float2bfloat16_rn(b);
    __nv_bfloat162 h2; h2.x = ha; h2.y = hb;
    __nv_bfloat162 l2;
    l2.x = __float2bfloat16_rn(a - __bfloat162float(ha));
    l2.y = __float2bfloat16_rn(b - __bfloat162float(hb));
    hi = *(uint32_t*)&h2; lo = *(uint32_t*)&l2;
}
__device__ __forceinline__ uint32_t pack_bf2(float a, float b) {
    __nv_bfloat162 h2; h2.x = __float2bfloat16_rn(a); h2.y = __float2bfloat16_rn(b);
    return *(uint32_t*)&h2;
}
// exp2 on FMA pipe: deg-5 poly + exponent splice.  arg <= 0, clamped at -125.
__device__ __forceinline__ float exp2p(float t) {
    t = fmaxf(t, -125.0f);
    float tr = t + 12582912.0f;                       // round to nearest int
    int   n  = __float_as_int(tr) - 0x4B400000;
    float f  = t - (tr - 12582912.0f);                // f in [-0.5, 0.5]
    float p  = 1.3333558146e-3f;
    p = fmaf(p, f, 9.6181291076e-3f);
    p = fmaf(p, f, 5.5504108665e-2f);
    p = fmaf(p, f, 2.4022650696e-1f);
    p = fmaf(p, f, 6.9314718056e-1f);
    p = fmaf(p, f, 1.0f);
    return __int_as_float(__float_as_int(p) + (n << 23));
}

// ---------------------------------------------------------------------------
// Prepass A: fp32 -> bf16 hi/lo (row-major preserved)
// ---------------------------------------------------------------------------
__global__ __launch_bounds__(256) void cvt_kernel(const float4* __restrict__ src,
                                                  uint32_t* __restrict__ hi,
                                                  uint32_t* __restrict__ lo, int n4)
{
    int i = blockIdx.x * 256 + threadIdx.x;
    if (i >= n4) return;
    float4 x = src[i];
    uint32_t h0, l0, h1, l1;
    pack_hilo(x.x, x.y, h0, l0);
    pack_hilo(x.z, x.w, h1, l1);
    hi[i * 2 + 0] = h0; hi[i * 2 + 1] = h1;
    lo[i * 2 + 0] = l0; lo[i * 2 + 1] = l1;
}

// Prepass B: transpose + convert weights.  src [bz][R][C] fp32 -> [bz][C][R] bf16 hi/lo
__global__ void trcvt_kernel(const float* __restrict__ src,
                             __nv_bfloat16* __restrict__ dhi, __nv_bfloat16* __restrict__ dlo,
                             int R, int C)
{
    __shared__ float t[32][33];
    const int bz = blockIdx.z;
    const int c0 = blockIdx.x * 32, r0 = blockIdx.y * 32;
    const int tx = threadIdx.x, ty = threadIdx.y;
    const float* s = src + (size_t)bz * R * C;
#pragma unroll
    for (int i = 0; i < 4; i++)
        t[ty + 8 * i][tx] = s[(size_t)(r0 + ty + 8 * i) * C + c0 + tx];
    __syncthreads();
#pragma unroll
    for (int i = 0; i < 4; i++) {
        float v = t[tx][ty + 8 * i];
        __nv_bfloat16 h = __float2bfloat16_rn(v);
        __nv_bfloat16 l = __float2bfloat16_rn(v - __bfloat162float(h));
        size_t o = (size_t)bz * C * R + (size_t)(c0 + ty + 8 * i) * R + r0 + tx;
        dhi[o] = h; dlo[o] = l;
    }
}

// ---------------------------------------------------------------------------
// HMMA GEMM (same core as R4), epilogue writes bf16 hi/lo for modes 0/1/2/4.
// mode 0: oh0/ol0=QW(+aux0), oh1/ol1=QR(+aux1), bnlh pairs
// mode 1/2: oh0/ol0(+aux0), bnlh pairs
// mode 3: fp32 out0 = D + aux0[col] + aux2[m*D+col]
// mode 4: oh0/ol0, rp layout [n][r][h] pairs
// ---------------------------------------------------------------------------
#define STRIDE 80

__global__ __launch_bounds__(256) void hgemm(
    const char* __restrict__ Ahi, const char* __restrict__ Alo,
    const char* __restrict__ Bhi, const char* __restrict__ Blo,
    const float* __restrict__ aux0, const float* __restrict__ aux1,
    const float* __restrict__ aux2, float* __restrict__ out0,
    uint32_t* __restrict__ oh0, uint32_t* __restrict__ ol0,
    uint32_t* __restrict__ oh1, uint32_t* __restrict__ ol1, int mode)
{
    __shared__ char sA[2][128 * STRIDE];
    __shared__ char sB[2][128 * STRIDE];

    const int tid = threadIdx.x, lane = tid & 31, wid = tid >> 5;
    const int wm = wid >> 1, wn = wid & 1;
    const int m0 = blockIdx.y * 128, n0 = blockIdx.x * 128;

    float c[2][8][4] = {};

    const int lrow = tid >> 1;
    const int lseg = (tid & 1) * 32;
    const size_t gA = (size_t)(m0 + lrow) * KBYTES + lseg;
    const size_t gB = (size_t)(n0 + lrow) * KBYTES + lseg;
    const int srow = lrow * STRIDE + lseg;
    const char* gp0 = Ahi + gA; const char* gp1 = Alo + gA;
    const char* gp2 = Bhi + gB; const char* gp3 = Blo + gB;
    char* sp0 = sA[0] + srow;  char* sp1 = sA[1] + srow;
    char* sp2 = sB[0] + srow;  char* sp3 = sB[1] + srow;

    const uint32_t aBaseHi = smem_u32(sA[0]), aBaseLo = smem_u32(sA[1]);
    const uint32_t bBaseHi = smem_u32(sB[0]), bBaseLo = smem_u32(sB[1]);
    const int arow_in = (lane & 7) + ((lane >> 3) & 1) * 8;
    const int ak16    = (lane >> 4) * 16;
    const int brow_in = (lane & 7) + (lane >> 4) * 8;
    const int bk16    = ((lane >> 3) & 1) * 16;
    const uint32_t aOffHi = aBaseHi + (wm * 32 + arow_in) * STRIDE + ak16;
    const uint32_t aOffLo = aBaseLo + (wm * 32 + arow_in) * STRIDE + ak16;
    const uint32_t bOffHi = bBaseHi + (wn * 64 + brow_in) * STRIDE + bk16;
    const uint32_t bOffLo = bBaseLo + (wn * 64 + brow_in) * STRIDE + bk16;

    uint4 pf0a, pf0b, pf1a, pf1b, pf2a, pf2b, pf3a, pf3b;
    pf0a = *(const uint4*)(gp0);      pf0b = *(const uint4*)(gp0 + 16);
    pf1a = *(const uint4*)(gp1);      pf1b = *(const uint4*)(gp1 + 16);
    pf2a = *(const uint4*)(gp2);      pf2b = *(const uint4*)(gp2 + 16);
    pf3a = *(const uint4*)(gp3);      pf3b = *(const uint4*)(gp3 + 16);

    for (int ck = 0; ck < 32; ck++) {
        *(uint4*)(sp0) = pf0a; *(uint4*)(sp0 + 16) = pf0b;
        *(uint4*)(sp1) = pf1a; *(uint4*)(sp1 + 16) = pf1b;
        *(uint4*)(sp2) = pf2a; *(uint4*)(sp2 + 16) = pf2b;
        *(uint4*)(sp3) = pf3a; *(uint4*)(sp3 + 16) = pf3b;
        __syncthreads();
        if (ck < 31) {
            int off = (ck + 1) * 64;
            pf0a = *(const uint4*)(gp0 + off); pf0b = *(const uint4*)(gp0 + off + 16);
            pf1a = *(const uint4*)(gp1 + off); pf1b = *(const uint4*)(gp1 + off + 16);
            pf2a = *(const uint4*)(gp2 + off); pf2b = *(const uint4*)(gp2 + off + 16);
            pf3a = *(const uint4*)(gp3 + off); pf3b = *(const uint4*)(gp3 + off + 16);
        }
#pragma unroll
        for (int ks = 0; ks < 2; ks++) {
            const int kb = ks * 32;
            uint32_t ah[2][4], al[2][4];
#pragma unroll
            for (int mt = 0; mt < 2; mt++) {
                ldmx4(ah[mt], aOffHi + mt * (16 * STRIDE) + kb);
                ldmx4(al[mt], aOffLo + mt * (16 * STRIDE) + kb);
            }
#pragma unroll
            for (int ntp = 0; ntp < 4; ntp++) {
                uint32_t bh[4], bl[4];
                ldmx4(bh, bOffHi + ntp * (16 * STRIDE) + kb);
                ldmx4(bl, bOffLo + ntp * (16 * STRIDE) + kb);
#pragma unroll
                for (int mt = 0; mt < 2; mt++) {
                    mma16816(c[mt][ntp * 2 + 0], ah[mt], bh + 0);
                    mma16816(c[mt][ntp * 2 + 1], ah[mt], bh + 2);
                    mma16816(c[mt][ntp * 2 + 0], ah[mt], bl + 0);
                    mma16816(c[mt][ntp * 2 + 1], ah[mt], bl + 2);
                    mma16816(c[mt][ntp * 2 + 0], al[mt], bh + 0);
                    mma16816(c[mt][ntp * 2 + 1], al[mt], bh + 2);
                }
            }
        }
        __syncthreads();
    }

    const int g = lane >> 2, tg = lane & 3;
#pragma unroll
    for (int mt = 0; mt < 2; mt++) {
#pragma unroll
        for (int half = 0; half < 2; half++) {
            const int m = m0 + wm * 32 + mt * 16 + g + half * 8;
#pragma unroll
            for (int nt = 0; nt < 8; nt++) {
                float v0 = c[mt][nt][half * 2 + 0];
                float v1 = c[mt][nt][half * 2 + 1];
                const int coln = n0 + wn * 64 + nt * 8 + tg * 2;
                if (mode == 3) {
                    size_t o = (size_t)m * DD + coln;
                    float2 res = *(const float2*)(aux2 + o);
                    *(float2*)(out0 + o) =
                        make_float2(v0 + aux0[coln] + res.x, v1 + aux0[coln + 1] + res.y);
                } else if (mode == 4) {
                    int hd = coln >> 6, h = coln & 63;
                    size_t o = ((size_t)hd * RR + m) * HH + h;
                    uint32_t hi, lo;
                    pack_hilo(v0, v1, hi, lo);
                    oh0[o >> 1] = hi; ol0[o >> 1] = lo;
                } else {
                    int hd = coln >> 6, h = coln & 63;
                    int b = m >> 10, l = m & 1023;
                    size_t o = ((size_t)(b * NH + hd) * LL + l) * HH + h;
                    uint32_t hi, lo;
                    pack_hilo(v0 + aux0[coln], v1 + aux0[coln + 1], hi, lo);
                    oh0[o >> 1] = hi; ol0[o >> 1] = lo;
                    if (mode == 0) {
                        pack_hilo(v0 + aux1[coln], v1 + aux1[coln + 1], hi, lo);
                        oh1[o >> 1] = hi; ol1[o >> 1] = lo;
                    }
                }
            }
        }
    }
}

// ---------------------------------------------------------------------------
// HMMA flash attention with relative-position band.
// CTA: 64 q-rows x 64 k-cols, 128 threads (4 warps, 16 rows each).
// smem: K hi/lo, V hi/lo (9216B each), U = union(R hi/lo | pos | Q staging), pen.
// ---------------------------------------------------------------------------
#define AST   144
#define POSW  132
#define OFF_KH 0
#define OFF_KL 9216
#define OFF_VH 18432
#define OFF_VL 27648
#define OFF_U  36864
#define OFF_PEN 73728
#define ATTN_BYTES 73984
#define SCALE2F (0.125f * LOG2E)

__global__ __launch_bounds__(128) void attn2(const int* __restrict__ pad,
    const uint32_t* __restrict__ qwh, const uint32_t* __restrict__ qwl,
    const uint32_t* __restrict__ qrh, const uint32_t* __restrict__ qrl,
    const uint32_t* __restrict__ khh, const uint32_t* __restrict__ khl,
    const uint32_t* __restrict__ vhh, const uint32_t* __restrict__ vhl,
    const uint32_t* __restrict__ rph, const uint32_t* __restrict__ rpl,
    uint32_t* __restrict__ outh, uint32_t* __restrict__ outl)
{
    extern __shared__ char dyn[];
    float* pos  = (float*)(dyn + OFF_U);
    float* pen2 = (float*)(dyn + OFF_PEN);

    const int tid = threadIdx.x, lane = tid & 31, w = tid >> 5;
    const int g = lane >> 2, tg = lane & 3;
    const int bn = blockIdx.y, b = bn >> 4, n = bn & 15;
    const int l0 = blockIdx.x * 64;

    const uint32_t uD  = smem_u32(dyn);
    const uint32_t uKH = uD + OFF_KH, uKL = uD + OFF_KL;
    const uint32_t uVH = uD + OFF_VH, uVL = uD + OFF_VL;
    const uint32_t uRH = uD + OFF_U,  uRL = uD + OFF_U + 18432;

    // ldmatrix lane offsets
    const int arow = (lane & 7) + ((lane >> 3) & 1) * 8;
    const int ak16 = (lane >> 4) * 16;
    const int brow = (lane & 7) + (lane >> 4) * 8;
    const int bk16 = ((lane >> 3) & 1) * 16;
    const int vrow = (lane & 7) + ((lane >> 3) & 1) * 8;
    const int vsel = (lane >> 4) * 16;

    // ---- Prologue: stage Q tiles (QWh/QWl/QRh/QRl) in U, extract A-frags ----
    const int lrow = tid >> 1, lseg = (tid & 1) * 64;
    {
        const size_t qoff = ((size_t)(bn * LL + l0 + lrow) << 7) + lseg;
        const int dstrow = lrow * AST + lseg;
        const uint4* s;
        uint4* d;
#define QCP(buf, at) \
        s = (const uint4*)((const char*)(buf) + qoff); \
        d = (uint4*)(dyn + OFF_U + (at) + dstrow); \
        d[0] = s[0]; d[1] = s[1]; d[2] = s[2]; d[3] = s[3];
        QCP(qwh, 0) QCP(qwl, 9216) QCP(qrh, 18432) QCP(qrl, 27648)
#undef QCP
    }
    __syncthreads();
    uint32_t fqwh[4][4], fqwl[4][4], fqrh[4][4], fqrl[4][4];
    {
        const uint32_t ao = uD + OFF_U + (w * 16 + arow) * AST + ak16;
#pragma unroll
        for (int ks = 0; ks < 4; ks++) {
            ldmx4(fqwh[ks], ao + ks * 32);
            ldmx4(fqwl[ks], ao + 9216 + ks * 32);
            ldmx4(fqrh[ks], ao + 18432 + ks * 32);
            ldmx4(fqrl[ks], ao + 27648 + ks * 32);
        }
    }

    float o[8][4] = {};
    float mrow[2] = {-INFINITY, -INFINITY};
    float lrowv[2] = {0.f, 0.f};

    for (int kt = 0; kt < LL / 64; kt++) {
        const int m0 = kt * 64;
        const int rel0 = LL + m0 - l0 - 63;

        __syncthreads();    // previous iter (or prologue frag loads) done
        // ---- loads ----
        {
            const size_t kv = ((size_t)(bn * LL + m0 + lrow) << 7) + lseg;
            const int dr = lrow * AST + lseg;
            const uint4* s; uint4* d;
#define KCP(buf, at) \
            s = (const uint4*)((const char*)(buf) + kv); \
            d = (uint4*)(dyn + (at) + dr); \
            d[0] = s[0]; d[1] = s[1]; d[2] = s[2]; d[3] = s[3];
            KCP(khh, OFF_KH) KCP(khl, OFF_KL) KCP(vhh, OFF_VH) KCP(vhl, OFF_VL)
#undef KCP
            int rel = rel0 + tid;
            rel = rel < 0 ? 0 : (rel > RR - 1 ? RR - 1 : rel);
            const uint4* rs = (const uint4*)((const char*)rph + (((size_t)(n * RR + rel)) << 7));
            uint4* rd = (uint4*)(dyn + OFF_U + tid * AST);
#pragma unroll
            for (int j = 0; j < 8; j++) rd[j] = rs[j];
            rs = (const uint4*)((const char*)rpl + (((size_t)(n * RR + rel)) << 7));
            rd = (uint4*)(dyn + OFF_U + 18432 + tid * AST);
#pragma unroll
            for (int j = 0; j < 8; j++) rd[j] = rs[j];
            if (tid < 64)
                pen2[tid] = pad[b * LL + m0 + tid] ? (-1.0e6f * LOG2E) : 0.0f;
        }
        __syncthreads();

        // ---- band MMA: pos[i][c] = QR . R^T, 16 n-tiles over c ----
        float bfr[16][4] = {};
#pragma unroll
        for (int ks = 0; ks < 4; ks++) {
#pragma unroll
            for (int np = 0; np < 8; np++) {
                uint32_t bh[4], bl[4];
                const uint32_t ro = (np * 16 + brow) * AST + bk16 + ks * 32;
                ldmx4(bh, uRH + ro);
                ldmx4(bl, uRL + ro);
                mma16816(bfr[np * 2 + 0], fqrh[ks], bh + 0);
                mma16816(bfr[np * 2 + 1], fqrh[ks], bh + 2);
                mma16816(bfr[np * 2 + 0], fqrh[ks], bl + 0);
                mma16816(bfr[np * 2 + 1], fqrh[ks], bl + 2);
                mma16816(bfr[np * 2 + 0], fqrl[ks], bh + 0);
                mma16816(bfr[np * 2 + 1], fqrl[ks], bh + 2);
            }
        }
        __syncthreads();    // all warps done reading R before pos overwrites U

        {
            float* p0 = pos + (w * 16 + g) * POSW + tg * 2;
            float* p1 = pos + (w * 16 + g + 8) * POSW + tg * 2;
#pragma unroll
            for (int nt = 0; nt < 16; nt++) {
                *(float2*)(p0 + nt * 8) = make_float2(bfr[nt][0], bfr[nt][1]);
                *(float2*)(p1 + nt * 8) = make_float2(bfr[nt][2], bfr[nt][3]);
            }
        }

        // ---- score MMA: S = QW . K^T ----
        float sfr[8][4] = {};
#pragma unroll
        for (int ks = 0; ks < 4; ks++) {
#pragma unroll
            for (int np = 0; np < 4; np++) {
                uint32_t bh[4], bl[4];
                const uint32_t ro = (np * 16 + brow) * AST + bk16 + ks * 32;
                ldmx4(bh, uKH + ro);
                ldmx4(bl, uKL + ro);
                mma16816(sfr[np * 2 + 0], fqwh[ks], bh + 0);
                mma16816(sfr[np * 2 + 1], fqwh[ks], bh + 2);
                mma16816(sfr[np * 2 + 0], fqwh[ks], bl + 0);
                mma16816(sfr[np * 2 + 1], fqwh[ks], bl + 2);
                mma16816(sfr[np * 2 + 0], fqwl[ks], bh + 0);
                mma16816(sfr[np * 2 + 1], fqwl[ks], bh + 2);
            }
        }
        __syncwarp();       // pos written by this warp, read below (warp-local rows)

        // ---- gather band + softmax (base-2, poly exp on FMA pipe) ----
#pragma unroll
        for (int r2 = 0; r2 < 2; r2++) {
            const int i = w * 16 + g + r2 * 8;
            const float* pr = pos + i * POSW + (63 - i);
            float mx = -INFINITY;
#pragma unroll
            for (int nt = 0; nt < 8; nt++) {
#pragma unroll
                for (int v2 = 0; v2 < 2; v2++) {
                    const int j = nt * 8 + tg * 2 + v2;
                    float sc = sfr[nt][r2 * 2 + v2] + pr[j];
                    float t = fmaf(sc, SCALE2F, pen2[j]);
                    sfr[nt][r2 * 2 + v2] = t;
                    mx = fmaxf(mx, t);
                }
            }
            mx = fmaxf(mx, __shfl_xor_sync(0xffffffffu, mx, 1));
            mx = fmaxf(mx, __shfl_xor_sync(0xffffffffu, mx, 2));
            const float mnew = fmaxf(mrow[r2], mx);
            const float alpha = exp2p(mrow[r2] - mnew);
            mrow[r2] = mnew;
            float ssum = 0.f;
#pragma unroll
            for (int nt = 0; nt < 8; nt++) {
#pragma unroll
                for (int v2 = 0; v2 < 2; v2++) {
                    float p = exp2p(sfr[nt][r2 * 2 + v2] - mnew);
                    sfr[nt][r2 * 2 + v2] = p;
                    ssum += p;
                }
            }
            ssum += __shfl_xor_sync(0xffffffffu, ssum, 1);
            ssum += __shfl_xor_sync(0xffffffffu, ssum, 2);
            lrowv[r2] = lrowv[r2] * alpha + ssum;
#pragma unroll
            for (int ht = 0; ht < 8; ht++) {
                o[ht][r2 * 2 + 0] *= alpha;
                o[ht][r2 * 2 + 1] *= alpha;
            }
        }

        // ---- PV: O += P . V  (P from regs, V^T via ldmatrix.trans) ----
#pragma unroll
        for (int ks = 0; ks < 4; ks++) {
            uint32_t aph[4], apl[4];
#pragma unroll
            for (int q2 = 0; q2 < 2; q2++) {
                const float* f = sfr[2 * ks + q2];
                __nv_bfloat16 h0 = __float2bfloat16_rn(f[0]);
                __nv_bfloat16 h1 = __float2bfloat16_rn(f[1]);
                __nv_bfloat16 h2 = __float2bfloat16_rn(f[2]);
                __nv_bfloat16 h3 = __float2bfloat16_rn(f[3]);
                __nv_bfloat162 t;
                t.x = h0; t.y = h1; aph[q2 * 2 + 0] = *(uint32_t*)&t;
                t.x = h2; t.y = h3; aph[q2 * 2 + 1] = *(uint32_t*)&t;
                apl[q2 * 2 + 0] = pack_bf2(f[0] - __bfloat162float(h0),
                                           f[1] - __bfloat162float(h1));
                apl[q2 * 2 + 1] = pack_bf2(f[2] - __bfloat162float(h2),
                                           f[3] - __bfloat162float(h3));
            }
            const uint32_t vo = (ks * 16 + vrow) * AST + vsel;
#pragma unroll
            for (int hp = 0; hp < 4; hp++) {
                uint32_t vbh[4], vbl[4];
                ldmx4t(vbh, uVH + vo + hp * 32);
                ldmx4t(vbl, uVL + vo + hp * 32);
                mma16816(o[hp * 2 + 0], aph, vbh + 0);
                mma16816(o[hp * 2 + 1], aph, vbh + 2);
                mma16816(o[hp * 2 + 0], aph, vbl + 0);
                mma16816(o[hp * 2 + 1], aph, vbl + 2);
                mma16816(o[hp * 2 + 0], apl, vbh + 0);
                mma16816(o[hp * 2 + 1], apl, vbh + 2);
            }
        }
    }

    // ---- epilogue: normalize, convert hi/lo, write [(b,l)][(n,h)] pairs ----
#pragma unroll
    for (int r2 = 0; r2 < 2; r2++) {
        const int i = w * 16 + g + r2 * 8;
        const int rowg = b * LL + l0 + i;
        const float inv = 1.0f / lrowv[r2];
#pragma unroll
        for (int ht = 0; ht < 8; ht++) {
            float v0 = o[ht][r2 * 2 + 0] * inv;
            float v1 = o[ht][r2 * 2 + 1] * inv;
            const int col = n * 64 + ht * 8 + tg * 2;
            uint32_t hi, lo;
            pack_hilo(v0, v1, hi, lo);
            outh[(size_t)rowg * 512 + (col >> 1)] = hi;
            outl[(size_t)rowg * 512 + (col >> 1)] = lo;
        }
    }
}

// ---------------------------------------------------------------------------
// LayerNorm
// ---------------------------------------------------------------------------
__global__ __launch_bounds__(256) void ln_kernel(
    float* __restrict__ X, const float* __restrict__ g, const float* __restrict__ bta)
{
    __shared__ float red[8];
    const int row = blockIdx.x;
    const int t   = threadIdx.x;
    float4 x = *(float4*)(X + (size_t)row * DD + t * 4);

    float s = x.x + x.y + x.z + x.w;
#pragma unroll
    for (int d = 16; d; d >>= 1) s += __shfl_xor_sync(0xffffffffu, s, d);
    if ((t & 31) == 0) red[t >> 5] = s;
    __syncthreads();
    float tot = red[0] + red[1] + red[2] + red[3] + red[4] + red[5] + red[6] + red[7];
    float mu = tot * (1.0f / DD);
    __syncthreads();

    float dx0 = x.x - mu, dx1 = x.y - mu, dx2 = x.z - mu, dx3 = x.w - mu;
    float sq = dx0 * dx0 + dx1 * dx1 + dx2 * dx2 + dx3 * dx3;
#pragma unroll
    for (int d = 16; d; d >>= 1) sq += __shfl_xor_sync(0xffffffffu, sq, d);
    if ((t & 31) == 0) red[t >> 5] = sq;
    __syncthreads();
    float var = (red[0] + red[1] + red[2] + red[3] + red[4] + red[5] + red[6] + red[7]) * (1.0f / DD);
    float rs = rsqrtf(var + 1e-5f);

    float4 gg = *(const float4*)(g + t * 4);
    float4 bb = *(const float4*)(bta + t * 4);
    float4 y = make_float4(dx0 * rs * gg.x + bb.x, dx1 * rs * gg.y + bb.y,
                           dx2 * rs * gg.z + bb.z, dx3 * rs * gg.w + bb.w);
    *(float4*)(X + (size_t)row * DD + t * 4) = y;
}

// ---------------------------------------------------------------------------
// Launch
// ---------------------------------------------------------------------------
extern "C" void kernel_launch(void* const* d_in, const int* in_sizes, int n_in,
                              void* d_out, int out_size)
{
    const float* q   = (const float*)d_in[0];
    const float* k   = (const float*)d_in[1];
    const float* v   = (const float*)d_in[2];
    const float* pe  = (const float*)d_in[3];
    const int*   pad = (const int*)d_in[4];
    const float* q_w = (const float*)d_in[5];
    const float* k_w = (const float*)d_in[6];
    const float* k_b = (const float*)d_in[7];
    const float* v_w = (const float*)d_in[8];
    const float* v_b = (const float*)d_in[9];
    const float* rwb = (const float*)d_in[10];
    const float* rrb = (const float*)d_in[11];
    const float* r_k = (const float*)d_in[12];
    const float* pw  = (const float*)d_in[13];
    const float* pb  = (const float*)d_in[14];
    const float* lg  = (const float*)d_in[15];
    const float* lb  = (const float*)d_in[16];
    float* out = (float*)d_out;

    cudaFuncSetAttribute(attn2, cudaFuncAttributeMaxDynamicSharedMemorySize, ATTN_BYTES);

    char *inhi, *inlo, *wthi, *wtlo;
    cudaGetSymbolAddress((void**)&inhi, g_INhi4);
    cudaGetSymbolAddress((void**)&inlo, g_INlo4);
    cudaGetSymbolAddress((void**)&wthi, g_WThi4);
    cudaGetSymbolAddress((void**)&wtlo, g_WTlo4);
    uint32_t *qwh, *qwl, *qrh, *qrl, *khh, *khl, *vhh, *vhl, *rph, *rpl;
    cudaGetSymbolAddress((void**)&qwh, g_QWh2);
    cudaGetSymbolAddress((void**)&qwl, g_QWl2);
    cudaGetSymbolAddress((void**)&qrh, g_QRh2);
    cudaGetSymbolAddress((void**)&qrl, g_QRl2);
    cudaGetSymbolAddress((void**)&khh, g_KHh2);
    cudaGetSymbolAddress((void**)&khl, g_KHl2);
    cudaGetSymbolAddress((void**)&vhh, g_VHh2);
    cudaGetSymbolAddress((void**)&vhl, g_VHl2);
    cudaGetSymbolAddress((void**)&rph, g_RPh2);
    cudaGetSymbolAddress((void**)&rpl, g_RPl2);

    dim3 gg(8, 32);
    dim3 tr(32, 8);
    const int n4_in = BB * LL * DD / 4;

    // ---- q projection -> QW/QR bf16 hi/lo ----
    cvt_kernel<<<(n4_in + 255) / 256, 256>>>((const float4*)q, (uint32_t*)inhi, (uint32_t*)inlo, n4_in);
    trcvt_kernel<<<dim3(32, 32, 1), tr>>>(q_w, (__nv_bfloat16*)wthi, (__nv_bfloat16*)wtlo, DD, DD);
    hgemm<<<gg, 256>>>(inhi, inlo, wthi, wtlo, rwb, rrb, nullptr, nullptr, qwh, qwl, qrh, qrl, 0);
    // ---- k projection ----
    cvt_kernel<<<(n4_in + 255) / 256, 256>>>((const float4*)k, (uint32_t*)inhi, (uint32_t*)inlo, n4_in);
    trcvt_kernel<<<dim3(32, 32, 1), tr>>>(k_w, (__nv_bfloat16*)wthi, (__nv_bfloat16*)wtlo, DD, DD);
    hgemm<<<gg, 256>>>(inhi, inlo, wthi, wtlo, k_b, nullptr, nullptr, nullptr, khh, khl, nullptr, nullptr, 1);
    // ---- v projection ----
    cvt_kernel<<<(n4_in + 255) / 256, 256>>>((const float4*)v, (uint32_t*)inhi, (uint32_t*)inlo, n4_in);
    trcvt_kernel<<<dim3(32, 32, 1), tr>>>(v_w, (__nv_bfloat16*)wthi, (__nv_bfloat16*)wtlo, DD, DD);
    hgemm<<<gg, 256>>>(inhi, inlo, wthi, wtlo, v_b, nullptr, nullptr, nullptr, vhh, vhl, nullptr, nullptr, 2);
    // ---- rp projection ----
    const int n4_pe = RR * DD / 4;
    cvt_kernel<<<(n4_pe + 255) / 256, 256>>>((const float4*)pe, (uint32_t*)inhi, (uint32_t*)inlo, n4_pe);
    trcvt_kernel<<<dim3(2, 32, 16), tr>>>(r_k, (__nv_bfloat16*)wthi, (__nv_bfloat16*)wtlo, DD, HH);
    hgemm<<<dim3(8, 16), 256>>>(inhi, inlo, wthi, wtlo, nullptr, nullptr, nullptr, nullptr, rph, rpl, nullptr, nullptr, 4);
    // ---- attention (writes post-GEMM A operand into g_IN hi/lo) ----
    attn2<<<dim3(LL / 64, BB * NH), 128, ATTN_BYTES>>>(pad, qwh, qwl, qrh, qrl,
                                                       khh, khl, vhh, vhl, rph, rpl,
                                                       (uint32_t*)inhi, (uint32_t*)inlo);
    // ---- post projection + residual ----
    trcvt_kernel<<<dim3(32, 32, 1), tr>>>(pw, (__nv_bfloat16*)wthi, (__nv_bfloat16*)wtlo, DD, DD);
    hgemm<<<gg, 256>>>(inhi, inlo, wthi, wtlo, pb, nullptr, q, out, nullptr, nullptr, nullptr, nullptr, 3);
    // ---- layernorm ----
    ln_kernel<<<BB * LL, 256>>>(out, lg, lb);
}